// round 7
// baseline (speedup 1.0000x reference)
#include <cuda_runtime.h>
#include <math.h>

// Problem constants
#define NB    4
#define DIMC  384
#define RES   56
#define NTOK  3136          // 56*56
#define TD    192
#define CSC   96

#define LOG2E 1.4426950408889634f
#define CS_SCALE 0.14433756729740643f   // 1/sqrt(48)
#define DN_SCALE 0.125f                 // 1/sqrt(64)

// ---------------------------------------------------------------------------
// Scratch (static device arrays; no allocation anywhere)
// ---------------------------------------------------------------------------
__device__ float g_wc[2][576 * 384];                 // combined (qkv_w @ proj_w), [line][j*384+c]
__device__ float g_qkv[2][NB * NTOK * 576];          // [line][((b*3136)+n)*576 + j]

// ---------------------------------------------------------------------------
// Kernel 1: combined weights  Wc[j][c] = sum_t qkv_w[j][t] * proj_w[t][c]
// grid (576, 2), block 384
// ---------------------------------------------------------------------------
__global__ void combine_w_kernel(const float* __restrict__ p1,
                                 const float* __restrict__ p2,
                                 const float* __restrict__ qu,
                                 const float* __restrict__ qd) {
    int j = blockIdx.x;
    int line = blockIdx.y;
    int c = threadIdx.x;                 // 0..383
    const float* qw = line ? qd : qu;    // [576][192]
    const float* pw = line ? p2 : p1;    // [192][384]
    const float* qrow = qw + j * 192;
    float s = 0.f;
#pragma unroll 8
    for (int t = 0; t < 192; t++)
        s += qrow[t] * pw[t * 384 + c];
    g_wc[line][j * 384 + c] = s;
}

// ---------------------------------------------------------------------------
// Kernel 2: qkv GEMM   out[b,n,j] = sum_c xa[b,c,n] * Wc[line][j,c]
// A is K-major-transposed: A[c][n] with n contiguous.
// 64x64 tile, K-chunk 16, 256 threads, 4x4 microtile.
// grid (49, 9, 8=b*2+line)
// ---------------------------------------------------------------------------
__global__ void __launch_bounds__(256) qkv_gemm_kernel(const float* __restrict__ xa) {
    __shared__ float Ash[16][64];
    __shared__ float Wsh[64][17];

    int z = blockIdx.z;
    int bb = z >> 1, line = z & 1;
    int n0 = blockIdx.x * 64;
    int j0 = blockIdx.y * 64;
    const float* A = xa + (size_t)bb * DIMC * NTOK;   // A[c][n]
    const float* W = g_wc[line];                      // W[j][c]
    int tid = threadIdx.x;
    int tn = tid & 15, tj = tid >> 4;

    int la_c = tid >> 4;          // 0..15
    int la_n = (tid & 15) * 4;    // 0..60
    int lw_j = tid >> 2;          // 0..63
    int lw_c = (tid & 3) * 4;     // 0..12

    float acc[4][4] = {};

    for (int c0 = 0; c0 < 384; c0 += 16) {
        float4 av = *(const float4*)&A[(size_t)(c0 + la_c) * NTOK + n0 + la_n];
        *(float4*)&Ash[la_c][la_n] = av;
        float4 wv = *(const float4*)&W[(j0 + lw_j) * 384 + c0 + lw_c];
        Wsh[lw_j][lw_c + 0] = wv.x;
        Wsh[lw_j][lw_c + 1] = wv.y;
        Wsh[lw_j][lw_c + 2] = wv.z;
        Wsh[lw_j][lw_c + 3] = wv.w;
        __syncthreads();
#pragma unroll
        for (int cc = 0; cc < 16; cc++) {
            float4 a4 = *(const float4*)&Ash[cc][tn * 4];
            float b0 = Wsh[tj * 4 + 0][cc];
            float b1 = Wsh[tj * 4 + 1][cc];
            float b2 = Wsh[tj * 4 + 2][cc];
            float b3 = Wsh[tj * 4 + 3][cc];
            acc[0][0] += a4.x * b0; acc[0][1] += a4.x * b1; acc[0][2] += a4.x * b2; acc[0][3] += a4.x * b3;
            acc[1][0] += a4.y * b0; acc[1][1] += a4.y * b1; acc[1][2] += a4.y * b2; acc[1][3] += a4.y * b3;
            acc[2][0] += a4.z * b0; acc[2][1] += a4.z * b1; acc[2][2] += a4.z * b2; acc[2][3] += a4.z * b3;
            acc[3][0] += a4.w * b0; acc[3][1] += a4.w * b1; acc[3][2] += a4.w * b2; acc[3][3] += a4.w * b3;
        }
        __syncthreads();
    }

    float* out = g_qkv[line] + (size_t)bb * NTOK * 576;
#pragma unroll
    for (int i = 0; i < 4; i++) {
        float4 o = make_float4(acc[i][0], acc[i][1], acc[i][2], acc[i][3]);
        *(float4*)&out[(size_t)(n0 + tn * 4 + i) * 576 + j0 + tj * 4] = o;
    }
}

// ---------------------------------------------------------------------------
// Kernel 3: CSWin attention + LePE (upper line)
// One CTA per (stripe window, head, batch, branch). 392 tokens, d=48, 2 heads.
// Full K,V in dynamic smem (150.5 KB). One query row per thread, online softmax.
// grid (8, 2, 8=b*2+branch), block 256, dyn smem = 2*392*48*4
// ---------------------------------------------------------------------------
#define CS_SMEM (2 * 392 * 48 * 4)

__global__ void __launch_bounds__(256) cswin_kernel(const float* __restrict__ lw0,
                                                    const float* __restrict__ lb0,
                                                    const float* __restrict__ lw1,
                                                    const float* __restrict__ lb1,
                                                    float* __restrict__ out) {
    extern __shared__ float sh[];
    float* Ks = sh;                 // [392][48]
    float* Vs = sh + 392 * 48;      // [392][48]
    __shared__ float wsh[48][9];
    __shared__ float bsh[48];

    int win = blockIdx.x;
    int hh  = blockIdx.y;
    int z   = blockIdx.z;
    int bb  = z >> 1, br = z & 1;
    // branch 0: stripe is 56(H) x 7(W), token = hl*7+wl, w = win*7+wl
    // branch 1: stripe is 7(H) x 56(W), token = hl*56+wl, h = win*7+hl
    int SW = br ? 56 : 7;
    int SH = br ? 7 : 56;
    int choff = br * CSC + hh * 48;
    const float* qkv = g_qkv[0] + (size_t)bb * NTOK * 576;
    int tid = threadIdx.x;

    // load K,V tiles (48 floats per token, contiguous in the 576-wide row)
    for (int e = tid; e < 392 * 12; e += 256) {
        int t = e / 12, d4 = (e % 12) * 4;
        int hl = t / SW, wl = t % SW;
        int h = br ? win * 7 + hl : hl;
        int w = br ? wl : win * 7 + wl;
        int n = h * RES + w;
        const float* row = qkv + (size_t)n * 576 + choff;
        *(float4*)&Ks[t * 48 + d4] = *(const float4*)&row[192 + d4];
        *(float4*)&Vs[t * 48 + d4] = *(const float4*)&row[384 + d4];
    }
    // LePE weights for this head's 48 channels
    const float* lw = br ? lw1 : lw0;
    const float* lb = br ? lb1 : lb0;
    for (int e = tid; e < 48 * 9; e += 256) {
        int d = e / 9, k = e % 9;
        wsh[d][k] = lw[(hh * 48 + d) * 9 + k];
    }
    if (tid < 48) bsh[tid] = lb[hh * 48 + tid];
    __syncthreads();

    const float qscale = CS_SCALE * LOG2E;

    for (int r = tid; r < 392; r += 256) {
        int hl = r / SW, wl = r % SW;
        int h = br ? win * 7 + hl : hl;
        int w = br ? wl : win * 7 + wl;
        int n = h * RES + w;
        const float* qrow = qkv + (size_t)n * 576 + choff;

        float q[48];
#pragma unroll
        for (int d4 = 0; d4 < 48; d4 += 4) {
            float4 v = *(const float4*)&qrow[d4];
            q[d4 + 0] = v.x * qscale; q[d4 + 1] = v.y * qscale;
            q[d4 + 2] = v.z * qscale; q[d4 + 3] = v.w * qscale;
        }
        float m = -1e30f, l = 0.f;
        float acc[48];
#pragma unroll
        for (int d = 0; d < 48; d++) acc[d] = 0.f;

        for (int c0 = 0; c0 < 392; c0 += 14) {
            float s[14];
#pragma unroll
            for (int i = 0; i < 14; i++) {
                const float* kr = &Ks[(c0 + i) * 48];
                float sv = 0.f;
#pragma unroll
                for (int d4 = 0; d4 < 48; d4 += 4) {
                    float4 kv = *(const float4*)&kr[d4];
                    sv += q[d4] * kv.x + q[d4 + 1] * kv.y + q[d4 + 2] * kv.z + q[d4 + 3] * kv.w;
                }
                s[i] = sv;
            }
            float cm = s[0];
#pragma unroll
            for (int i = 1; i < 14; i++) cm = fmaxf(cm, s[i]);
            float mnew = fmaxf(m, cm);
            float rs = exp2f(m - mnew);
            l *= rs;
#pragma unroll
            for (int d = 0; d < 48; d++) acc[d] *= rs;
#pragma unroll
            for (int i = 0; i < 14; i++) {
                float p = exp2f(s[i] - mnew);
                l += p;
                const float* vr = &Vs[(c0 + i) * 48];
#pragma unroll
                for (int d4 = 0; d4 < 48; d4 += 4) {
                    float4 vv = *(const float4*)&vr[d4];
                    acc[d4 + 0] += p * vv.x; acc[d4 + 1] += p * vv.y;
                    acc[d4 + 2] += p * vv.z; acc[d4 + 3] += p * vv.w;
                }
            }
            m = mnew;
        }
        float inv = 1.f / l;

        // LePE: depthwise 3x3 on V, zero-padded at stripe borders
        float lep[48];
#pragma unroll
        for (int d = 0; d < 48; d++) lep[d] = bsh[d];
#pragma unroll
        for (int dy = -1; dy <= 1; dy++) {
#pragma unroll
            for (int dx = -1; dx <= 1; dx++) {
                int h2 = hl + dy, w2 = wl + dx;
                if (h2 < 0 || h2 >= SH || w2 < 0 || w2 >= SW) continue;
                const float* vr = &Vs[(h2 * SW + w2) * 48];
                int tap = (dy + 1) * 3 + (dx + 1);
#pragma unroll
                for (int d = 0; d < 48; d += 4) {
                    float4 vv = *(const float4*)&vr[d];
                    lep[d + 0] += vv.x * wsh[d + 0][tap];
                    lep[d + 1] += vv.y * wsh[d + 1][tap];
                    lep[d + 2] += vv.z * wsh[d + 2][tap];
                    lep[d + 3] += vv.w * wsh[d + 3][tap];
                }
            }
        }

        float* obase = out + ((size_t)bb * DIMC + br * CSC + hh * 48) * NTOK + n;
#pragma unroll
        for (int d = 0; d < 48; d++)
            obase[(size_t)d * NTOK] = acc[d] * inv + lep[d];
    }
}

// ---------------------------------------------------------------------------
// Kernel 4: global multi-head attention (lower line), flash-style,
// cp.async double-buffered K/V tiles in DYNAMIC smem (64 KB > 48 KB static cap).
// 3 heads, d=64, N=3136. CTA = 128 query rows (1/thread), K/V tiles of 64.
// grid (25, 3, 4), block 128, dyn smem = 4*64*64*4 = 65536
// ---------------------------------------------------------------------------
#define DN_SMEM (4 * 64 * 64 * 4)

__device__ __forceinline__ void cp_async16(void* smem_dst, const void* gsrc) {
    unsigned s = (unsigned)__cvta_generic_to_shared(smem_dst);
    asm volatile("cp.async.cg.shared.global [%0], [%1], 16;\n" :: "r"(s), "l"(gsrc));
}

__global__ void __launch_bounds__(128) attn_dn_kernel(float* __restrict__ out) {
    extern __shared__ float dnsh[];
    // layout: Ks[2][64][64], Vs[2][64][64]
    float* Ksb[2] = { dnsh,            dnsh + 64 * 64 };
    float* Vsb[2] = { dnsh + 2*64*64,  dnsh + 3*64*64 };

    int qt = blockIdx.x, hh = blockIdx.y, bb = blockIdx.z;
    const float* qkv = g_qkv[1] + (size_t)bb * NTOK * 576;
    int tid = threadIdx.x;
    int r = qt * 128 + tid;
    bool active = r < NTOK;

    const float qscale = DN_SCALE * LOG2E;
    float q[64], acc[64];
    float m = -1e30f, l = 0.f;
#pragma unroll
    for (int d = 0; d < 64; d++) acc[d] = 0.f;
    if (active) {
        const float* qrow = qkv + (size_t)r * 576 + hh * 64;
#pragma unroll
        for (int d4 = 0; d4 < 64; d4 += 4) {
            float4 v = *(const float4*)&qrow[d4];
            q[d4 + 0] = v.x * qscale; q[d4 + 1] = v.y * qscale;
            q[d4 + 2] = v.z * qscale; q[d4 + 3] = v.w * qscale;
        }
    }

    // --- async tile loader: 64 tokens x 64 floats for K and V ---
    int lt = tid >> 1;              // 0..63  token
    int ld = (tid & 1) * 32;        // 0 or 32: half-row start
    auto load_tile = [&](int kt, int buf) {
        const float* row = qkv + (size_t)(kt * 64 + lt) * 576 + hh * 64 + ld;
        float* kdst = Ksb[buf] + lt * 64 + ld;
        float* vdst = Vsb[buf] + lt * 64 + ld;
#pragma unroll
        for (int i = 0; i < 8; i++) {
            cp_async16(kdst + i * 4, row + 192 + i * 4);
            cp_async16(vdst + i * 4, row + 384 + i * 4);
        }
        asm volatile("cp.async.commit_group;\n" ::: "memory");
    };

    load_tile(0, 0);

    for (int kt = 0; kt < 49; kt++) {
        int cur = kt & 1;
        if (kt < 48) {
            load_tile(kt + 1, cur ^ 1);
            asm volatile("cp.async.wait_group 1;\n" ::: "memory");
        } else {
            asm volatile("cp.async.wait_group 0;\n" ::: "memory");
        }
        __syncthreads();

        const float* Kcur = Ksb[cur];
        const float* Vcur = Vsb[cur];
        if (active) {
#pragma unroll 1
            for (int c0 = 0; c0 < 64; c0 += 16) {
                float s[16];
#pragma unroll
                for (int i = 0; i < 16; i++) {
                    const float* kr = Kcur + (c0 + i) * 64;
                    float sv = 0.f;
#pragma unroll
                    for (int d4 = 0; d4 < 64; d4 += 4) {
                        float4 kv = *(const float4*)&kr[d4];
                        sv += q[d4] * kv.x + q[d4 + 1] * kv.y + q[d4 + 2] * kv.z + q[d4 + 3] * kv.w;
                    }
                    s[i] = sv;
                }
                float cm = s[0];
#pragma unroll
                for (int i = 1; i < 16; i++) cm = fmaxf(cm, s[i]);
                float mnew = fmaxf(m, cm);
                float rs = exp2f(m - mnew);
                l *= rs;
#pragma unroll
                for (int d = 0; d < 64; d++) acc[d] *= rs;
#pragma unroll
                for (int i = 0; i < 16; i++) {
                    float p = exp2f(s[i] - mnew);
                    l += p;
                    const float* vr = Vcur + (c0 + i) * 64;
#pragma unroll
                    for (int d4 = 0; d4 < 64; d4 += 4) {
                        float4 vv = *(const float4*)&vr[d4];
                        acc[d4 + 0] += p * vv.x; acc[d4 + 1] += p * vv.y;
                        acc[d4 + 2] += p * vv.z; acc[d4 + 3] += p * vv.w;
                    }
                }
                m = mnew;
            }
        }
        __syncthreads();   // all threads done reading buf `cur` before it is refilled
    }

    if (active) {
        float inv = 1.f / l;
        float* ob = out + ((size_t)bb * DIMC + TD + hh * 64) * NTOK + r;
#pragma unroll
        for (int d = 0; d < 64; d++)
            ob[(size_t)d * NTOK] = acc[d] * inv;
    }
}

// ---------------------------------------------------------------------------
// Launch
// ---------------------------------------------------------------------------
extern "C" void kernel_launch(void* const* d_in, const int* in_sizes, int n_in,
                              void* d_out, int out_size) {
    const float* xa      = (const float*)d_in[0];
    const float* proj1_w = (const float*)d_in[1];
    const float* proj2_w = (const float*)d_in[2];
    const float* qkv_u_w = (const float*)d_in[3];
    const float* qkv_d_w = (const float*)d_in[4];
    const float* lepe_w0 = (const float*)d_in[5];
    const float* lepe_b0 = (const float*)d_in[6];
    const float* lepe_w1 = (const float*)d_in[7];
    const float* lepe_b1 = (const float*)d_in[8];
    float* out = (float*)d_out;

    // 1) combined weights (Wqkv @ Wproj)
    combine_w_kernel<<<dim3(576, 2), 384>>>(proj1_w, proj2_w, qkv_u_w, qkv_d_w);

    // 2) fused proj+qkv GEMM for both lines
    qkv_gemm_kernel<<<dim3(49, 9, 8), 256>>>(xa);

    // 3) CSWin upper line (writes channels [0,192))
    cudaFuncSetAttribute(cswin_kernel, cudaFuncAttributeMaxDynamicSharedMemorySize, CS_SMEM);
    cswin_kernel<<<dim3(8, 2, 8), 256, CS_SMEM>>>(lepe_w0, lepe_b0, lepe_w1, lepe_b1, out);

    // 4) global attention lower line (writes channels [192,384))
    cudaFuncSetAttribute(attn_dn_kernel, cudaFuncAttributeMaxDynamicSharedMemorySize, DN_SMEM);
    attn_dn_kernel<<<dim3(25, 3, 4), 128, DN_SMEM>>>(out);
}